// round 2
// baseline (speedup 1.0000x reference)
#include <cuda_runtime.h>

// Hausdorff distance, batched N=8, grid 96x96, coords (i/96, j/96).
// haus[s] = max(directed(A\B -> B), directed(B\A -> A)), out = mean over s.
// Exact integer separable EDT:
//   phase 2: per-row 1D squared distance to nearest target in the row (two sweeps)
//   phase 3: per-column Felzenszwalb lower envelope: d2(i,j) = min_ii (i-ii)^2 + rd2(ii,j)
// All values < 2^24 so float envelope intersections are exact at integer points.

#define HD 96
#define WD 96
#define HW (HD * WD)

__device__ float        g_dir[64];     // [sample*2 + dir]
__device__ unsigned int g_count = 0;   // last-block-done counter (self-resetting)

__global__ void __launch_bounds__(256) hausdorff_fused_kernel(
    const float* __restrict__ pred, const float* __restrict__ targ,
    float* __restrict__ out, int n) {
    __shared__ unsigned short s_buf[HW];   // phase 1-2: tgt mask (byte view); phase 3+: d2 (ushort)
    __shared__ unsigned short s_rd2[HW];   // squared row distances (sentinel 200^2 = 40000)
    __shared__ int s_red[256];
    __shared__ int s_anyTgt;

    const int s   = blockIdx.x;
    const int dir = blockIdx.y;            // 0: tgt=B, src=A&~B ; 1: tgt=A, src=B&~A
    const int tid = threadIdx.x;

    const float* __restrict__ P = pred + s * HW;
    const float* __restrict__ T = targ + s * HW;
    unsigned char* s_tgt = (unsigned char*)s_buf;

    if (tid == 0) s_anyTgt = 0;

    // Phase 1: target mask (round(x)>0.5 <=> x>0.5 for x in [0,1))
    for (int p = tid; p < HW; p += 256) {
        float tv = dir ? P[p] : T[p];
        s_tgt[p] = (unsigned char)(tv > 0.5f);
    }
    __syncthreads();

    // Phase 2: per-row 1D distance (two sweeps), thread i owns row i
    if (tid < HD) {
        const int base = tid * WD;
        int d = 200, any = 0;
        for (int j = 0; j < WD; j++) {
            if (s_tgt[base + j]) { d = 0; any = 1; } else d = min(d + 1, 200);
            s_rd2[base + j] = (unsigned short)d;
        }
        d = 200;
        for (int j = WD - 1; j >= 0; j--) {
            if (s_tgt[base + j]) d = 0; else d = min(d + 1, 200);
            int v = min((int)s_rd2[base + j], d);
            s_rd2[base + j] = (unsigned short)(v * v);
        }
        if (any) atomicOr(&s_anyTgt, 1);
    }
    __syncthreads();

    // Phase 3: per-column exact EDT via lower envelope of parabolas.
    // Thread j owns column j. Writes d2 into s_buf (tgt mask is dead now).
    // Sentinel rows (rd2=40000) can never win: any real target row gives
    // d2 <= 95^2 + 95^2 = 18050 < 40000. Max stored value 95^2+40000 = 49025 < 65536.
    if (tid < WD) {
        const int j = tid;
        int   v[HD];
        float z[HD + 1];
        int k = 0;
        v[0] = 0; z[0] = -1e30f; z[1] = 1e30f;
        for (int q = 1; q < HD; q++) {
            float fq = (float)(q * q + (int)s_rd2[q * WD + j]);
            while (true) {
                int   vk = v[k];
                float fv = (float)(vk * vk + (int)s_rd2[vk * WD + j]);
                float sx = (fq - fv) / (float)(2 * (q - vk));
                if (sx <= z[k]) { k--; }
                else { k++; v[k] = q; z[k] = sx; z[k + 1] = 1e30f; break; }
            }
        }
        k = 0;
        for (int q = 0; q < HD; q++) {
            while (z[k + 1] < (float)q) k++;
            int vk = v[k];
            int dq = q - vk;
            int d2 = dq * dq + (int)s_rd2[vk * WD + j];
            s_buf[q * WD + j] = (unsigned short)d2;
        }
    }
    __syncthreads();

    // Phase 4: max of d2 over source pixels (src recomputed from L2-hot globals)
    int best = -1;
    for (int p = tid; p < HW; p += 256) {
        bool a = P[p] > 0.5f;
        bool b = T[p] > 0.5f;
        bool src = dir ? (b && !a) : (a && !b);
        if (src) best = max(best, (int)s_buf[p]);
    }
    s_red[tid] = best;
    __syncthreads();
    #pragma unroll
    for (int st = 128; st > 0; st >>= 1) {
        if (tid < st) s_red[tid] = max(s_red[tid], s_red[tid + st]);
        __syncthreads();
    }

    // Directed distance + fused last-block finisher
    if (tid == 0) {
        float r;
        if (s_red[0] < 0)   r = 0.0f;                               // empty source set
        else if (!s_anyTgt) r = 1e9f;                               // src nonempty, tgt empty
        else                r = sqrtf((float)s_red[0]) * (1.0f / 96.0f);
        g_dir[s * 2 + dir] = r;
        __threadfence();
        unsigned int t = atomicAdd(&g_count, 1);
        if (t == (unsigned int)(2 * n - 1)) {       // last block: finish + reset
            __threadfence();
            volatile float* gd = g_dir;
            float acc = 0.0f;
            for (int i = 0; i < n; i++)
                acc += fmaxf(gd[2 * i], gd[2 * i + 1]);
            out[0] = acc / (float)n;
            g_count = 0;                             // self-reset for next launch
        }
    }
}

extern "C" void kernel_launch(void* const* d_in, const int* in_sizes, int n_in,
                              void* d_out, int out_size) {
    const float* pred = (const float*)d_in[0];
    const float* targ = (const float*)d_in[1];
    float* out = (float*)d_out;
    int n = in_sizes[0] / HW;   // batch size (8)

    dim3 grid(n, 2);
    hausdorff_fused_kernel<<<grid, 256>>>(pred, targ, out, n);
}

// round 3
// speedup vs baseline: 5.9084x; 5.9084x over previous
#include <cuda_runtime.h>

// Hausdorff distance, batched N=8, grid 96x96, coords (i/96, j/96).
// haus[s] = max(directed(A\B -> B), directed(B\A -> A)), out = mean over s.
// Bitmask row-EDT (clz/ffs on packed row masks) + early-exit outward column scan.
// All distance math exact in integers; one sqrt at the end.

#define HD 96
#define WD 96
#define HW (HD * WD)
#define NWORDS (HW / 32)   // 288 ballot words per mask

__device__ float        g_dir[64];     // [sample*2 + dir]
__device__ unsigned int g_count = 0;   // last-block-done counter (self-resetting)

__global__ void __launch_bounds__(256) hausdorff_kernel(
    const float* __restrict__ pred, const float* __restrict__ targ,
    float* __restrict__ out, int n) {
    __shared__ unsigned int  s_am[NWORDS];   // pred mask bits
    __shared__ unsigned int  s_bm[NWORDS];   // targ mask bits
    __shared__ unsigned char s_rd[HW];       // per-pixel row distance (sentinel 200)
    __shared__ int s_red[8];
    __shared__ int s_anyTgt;

    const int s    = blockIdx.x;
    const int dir  = blockIdx.y;             // 0: tgt=B, src=A&~B ; 1: tgt=A, src=B&~A
    const int tid  = threadIdx.x;
    const int lane = tid & 31;
    const int wrp  = tid >> 5;

    const float* __restrict__ P = pred + s * HW;
    const float* __restrict__ T = targ + s * HW;

    if (tid == 0) s_anyTgt = 0;

    // ---- Phase 1: build bit masks via ballot (32 consecutive j in one row per word,
    //      since 96 = 3*32 each 32-aligned chunk stays within a row)
    #pragma unroll
    for (int k = 0; k < HW / 256; k++) {
        int p = tid + k * 256;
        unsigned am = __ballot_sync(0xffffffffu, P[p] > 0.5f);  // round(x)>0.5 <=> x>0.5
        unsigned bm = __ballot_sync(0xffffffffu, T[p] > 0.5f);
        if (lane == 0) {
            int w = wrp + k * 8;
            s_am[w] = am;
            s_bm[w] = bm;
        }
    }
    __syncthreads();

    const unsigned int* __restrict__ st = dir ? s_am : s_bm;   // target mask words

    // ---- Phase 2: per-pixel row distance from packed row mask (fully parallel)
    int anyT = 0;
    #pragma unroll
    for (int k = 0; k < HW / 256; k++) {
        int p = tid + k * 256;
        int i = p / WD;
        int j = p - i * WD;
        unsigned m0 = st[i * 3], m1 = st[i * 3 + 1], m2 = st[i * 3 + 2];
        anyT |= (m0 | m1 | m2);
        unsigned long long lo = (unsigned long long)m0 | ((unsigned long long)m1 << 32); // bits 0..63
        unsigned hi = m2;                                                                // bits 64..95
        int dl, dr;
        if (j < 64) {
            unsigned long long x = lo & (~0ULL >> (63 - j));       // bits 0..j
            dl = x ? (j - (63 - __clzll(x))) : 200;
            unsigned long long y = lo >> j;                        // bits j..63
            if (y)      dr = __ffsll(y) - 1;
            else if (hi) dr = (64 - j) + __ffs(hi) - 1;
            else        dr = 200;
        } else {
            unsigned x = hi & (~0u >> (95 - j));                   // bits 64..j
            if (x)      dl = j - (64 + 31 - __clz(x));
            else if (lo) dl = j - (63 - __clzll(lo));
            else        dl = 200;
            unsigned y = hi >> (j - 64);                           // bits j..95
            dr = y ? (__ffs(y) - 1) : 200;
        }
        s_rd[p] = (unsigned char)min(200, min(dl, dr));
    }
    if (anyT) atomicOr(&s_anyTgt, 1);
    __syncthreads();

    // ---- Phase 3+4: for each SOURCE pixel, outward column scan with early exit.
    // d2(i,j) = min_di di^2 + rd(i+-di, j)^2 ; break when di^2 >= best.
    int best = -1;
    for (int w = tid; w < NWORDS; w += 256) {
        unsigned srcw = dir ? (s_bm[w] & ~s_am[w]) : (s_am[w] & ~s_bm[w]);
        while (srcw) {
            int b = __ffs(srcw) - 1;
            srcw &= srcw - 1;
            int p = w * 32 + b;
            int i = p / WD;
            int j = p - i * WD;
            int r0 = s_rd[p];
            int bst = r0 * r0;
            for (int di = 1; di <= 95 && di * di < bst; di++) {
                int d2 = di * di;
                int u = i - di, v = i + di;
                if (u >= 0) { int r = s_rd[u * WD + j]; bst = min(bst, d2 + r * r); }
                if (v < HD) { int r = s_rd[v * WD + j]; bst = min(bst, d2 + r * r); }
            }
            best = max(best, bst);
        }
    }

    // ---- Block max-reduction (warp shuffle + 8-slot smem)
    #pragma unroll
    for (int off = 16; off > 0; off >>= 1)
        best = max(best, __shfl_xor_sync(0xffffffffu, best, off));
    if (lane == 0) s_red[wrp] = best;
    __syncthreads();
    if (tid == 0) {
        int m = s_red[0];
        #pragma unroll
        for (int k = 1; k < 8; k++) m = max(m, s_red[k]);
        float r;
        if (m < 0)           r = 0.0f;                           // empty source set
        else if (!s_anyTgt)  r = 1e9f;                           // src nonempty, tgt empty
        else                 r = sqrtf((float)m) * (1.0f / 96.0f);
        g_dir[s * 2 + dir] = r;
        __threadfence();
        unsigned int t = atomicAdd(&g_count, 1);
        if (t == (unsigned int)(2 * n - 1)) {                    // last block finishes
            __threadfence();
            volatile float* gd = g_dir;
            float acc = 0.0f;
            for (int i = 0; i < n; i++)
                acc += fmaxf(gd[2 * i], gd[2 * i + 1]);
            out[0] = acc / (float)n;
            g_count = 0;                                         // self-reset for next replay
        }
    }
}

extern "C" void kernel_launch(void* const* d_in, const int* in_sizes, int n_in,
                              void* d_out, int out_size) {
    const float* pred = (const float*)d_in[0];
    const float* targ = (const float*)d_in[1];
    float* out = (float*)d_out;
    int n = in_sizes[0] / HW;   // batch size (8)

    dim3 grid(n, 2);
    hausdorff_kernel<<<grid, 256>>>(pred, targ, out, n);
}

// round 4
// speedup vs baseline: 8.0433x; 1.3613x over previous
#include <cuda_runtime.h>

// Hausdorff distance, batched N=8, grid 96x96, coords (i/96, j/96).
// haus[s] = max(directed(A\B -> B), directed(B\A -> A)), out = mean over s.
// float4 loads -> nibble masks -> packed 96-bit row masks;
// row-EDT via clz/ffs (divergence-free: warp owns 3 rows, lane j in fixed ranges);
// directed distance via early-exit outward column scan over source bits only.

#define HD 96
#define WD 96
#define HW (HD * WD)
#define NWORDS (HW / 32)      // 288
#define NQUAD  (HW / 4)       // 2304 float4s / nibbles per mask
#define NT 1024

__device__ float        g_dir[64];
__device__ unsigned int g_count = 0;   // self-resetting last-block counter

static __device__ __forceinline__ unsigned pack_nib(unsigned x) {
    // 4 bytes each holding a nibble -> 16 packed bits
    return (x & 0xFu) | ((x >> 4) & 0xF0u) | ((x >> 8) & 0xF00u) | ((x >> 12) & 0xF000u);
}

__global__ void __launch_bounds__(NT) hausdorff_kernel(
    const float* __restrict__ pred, const float* __restrict__ targ,
    float* __restrict__ out, int n) {
    __shared__ unsigned char s_an[NQUAD];    // pred nibbles
    __shared__ unsigned char s_bn[NQUAD];    // targ nibbles
    __shared__ unsigned int  s_am[NWORDS];   // pred row-mask words
    __shared__ unsigned int  s_bm[NWORDS];   // targ row-mask words
    __shared__ unsigned char s_rd[HW];       // per-pixel row distance (sentinel 200)
    __shared__ int s_red[32];

    const int s    = blockIdx.x;
    const int dir  = blockIdx.y;             // 0: tgt=B, src=A&~B ; 1: tgt=A, src=B&~A
    const int tid  = threadIdx.x;
    const int lane = tid & 31;
    const int wrp  = tid >> 5;               // 0..31

    const float4* __restrict__ P4 = (const float4*)(pred + s * HW);
    const float4* __restrict__ T4 = (const float4*)(targ + s * HW);

    // ---- Phase 1a: vectorized loads -> nibbles  (round(x)>0.5 <=> x>0.5 on [0,1))
    for (int p = tid; p < NQUAD; p += NT) {
        float4 a = P4[p];
        float4 b = T4[p];
        unsigned na = (unsigned)(a.x > 0.5f) | ((unsigned)(a.y > 0.5f) << 1)
                    | ((unsigned)(a.z > 0.5f) << 2) | ((unsigned)(a.w > 0.5f) << 3);
        unsigned nb = (unsigned)(b.x > 0.5f) | ((unsigned)(b.y > 0.5f) << 1)
                    | ((unsigned)(b.z > 0.5f) << 2) | ((unsigned)(b.w > 0.5f) << 3);
        s_an[p] = (unsigned char)na;
        s_bn[p] = (unsigned char)nb;
    }
    __syncthreads();

    // ---- Phase 1b: pack 8 nibbles -> one 32-bit mask word (288 threads)
    int myTgtNonzero = 0;
    if (tid < NWORDS) {
        const unsigned* pa = (const unsigned*)s_an;
        const unsigned* pb = (const unsigned*)s_bn;
        unsigned am = pack_nib(pa[2 * tid]) | (pack_nib(pa[2 * tid + 1]) << 16);
        unsigned bm = pack_nib(pb[2 * tid]) | (pack_nib(pb[2 * tid + 1]) << 16);
        s_am[tid] = am;
        s_bm[tid] = bm;
        myTgtNonzero = (dir ? am : bm) != 0;
    }
    const int anyTgt = __syncthreads_or(myTgtNonzero);

    const unsigned int* __restrict__ st = dir ? s_am : s_bm;   // target mask words

    // ---- Phase 2: row distances. Warp w owns rows 3w..3w+2; lane handles
    // j = lane, lane+32, lane+64 (branch-free: j-range known per slot).
    {
        #pragma unroll
        for (int rr = 0; rr < 3; rr++) {
            const int i = wrp * 3 + rr;
            const unsigned m0 = st[i * 3], m1 = st[i * 3 + 1], m2 = st[i * 3 + 2];
            const unsigned long long lo = (unsigned long long)m0 | ((unsigned long long)m1 << 32);
            const unsigned hi = m2;
            // slot 0: j = lane (0..31)
            {
                const int j = lane;
                unsigned long long x = lo & (~0ULL >> (63 - j));
                int dl = x ? (j - (63 - __clzll(x))) : 200;
                unsigned long long y = lo >> j;
                int dr = y ? (__ffsll(y) - 1) : (hi ? (64 - j) + __ffs(hi) - 1 : 200);
                s_rd[i * WD + j] = (unsigned char)min(dl, dr);
            }
            // slot 1: j = lane+32 (32..63)
            {
                const int j = lane + 32;
                unsigned long long x = lo & (~0ULL >> (63 - j));
                int dl = x ? (j - (63 - __clzll(x))) : 200;
                unsigned long long y = lo >> j;
                int dr = y ? (__ffsll(y) - 1) : (hi ? (64 - j) + __ffs(hi) - 1 : 200);
                s_rd[i * WD + j] = (unsigned char)min(dl, dr);
            }
            // slot 2: j = lane+64 (64..95)
            {
                const int j = lane + 64;
                unsigned x = hi & (~0u >> (31 - lane));
                int dl;
                if (x)       dl = j - (64 + 31 - __clz(x));
                else if (lo) dl = j - (63 - __clzll(lo));
                else         dl = 200;
                unsigned y = hi >> lane;
                int dr = y ? (__ffs(y) - 1) : 200;
                s_rd[i * WD + j] = (unsigned char)min(dl, dr);
            }
        }
    }
    __syncthreads();

    // ---- Phase 3: per source pixel, outward column scan with early exit.
    int best = -1;
    if (tid < NWORDS) {
        unsigned srcw = dir ? (s_bm[tid] & ~s_am[tid]) : (s_am[tid] & ~s_bm[tid]);
        const int base = tid * 32;
        while (srcw) {
            int b = __ffs(srcw) - 1;
            srcw &= srcw - 1;
            int p = base + b;
            int i = p / WD;
            int j = p - i * WD;
            int r0 = s_rd[p];
            int bst = r0 * r0;
            for (int di = 1; di <= 95 && di * di < bst; di++) {
                int d2 = di * di;
                int u = i - di, v = i + di;
                if (u >= 0) { int r = s_rd[u * WD + j]; bst = min(bst, d2 + r * r); }
                if (v < HD) { int r = s_rd[v * WD + j]; bst = min(bst, d2 + r * r); }
            }
            best = max(best, bst);
        }
    }

    // ---- Block max-reduction
    #pragma unroll
    for (int off = 16; off > 0; off >>= 1)
        best = max(best, __shfl_xor_sync(0xffffffffu, best, off));
    if (lane == 0) s_red[wrp] = best;
    __syncthreads();
    if (tid == 0) {
        int m = s_red[0];
        #pragma unroll
        for (int k = 1; k < 32; k++) m = max(m, s_red[k]);
        float r;
        if (m < 0)       r = 0.0f;                       // empty source set
        else if (!anyTgt) r = 1e9f;                      // src nonempty, tgt empty
        else             r = sqrtf((float)m) * (1.0f / 96.0f);
        g_dir[s * 2 + dir] = r;
        __threadfence();
        unsigned int t = atomicAdd(&g_count, 1);
        if (t == (unsigned int)(2 * n - 1)) {            // last block: finish + reset
            __threadfence();
            volatile float* gd = g_dir;
            float acc = 0.0f;
            for (int i = 0; i < n; i++)
                acc += fmaxf(gd[2 * i], gd[2 * i + 1]);
            out[0] = acc / (float)n;
            g_count = 0;                                 // self-reset for next replay
        }
    }
}

extern "C" void kernel_launch(void* const* d_in, const int* in_sizes, int n_in,
                              void* d_out, int out_size) {
    const float* pred = (const float*)d_in[0];
    const float* targ = (const float*)d_in[1];
    float* out = (float*)d_out;
    int n = in_sizes[0] / HW;   // batch size (8)

    dim3 grid(n, 2);
    hausdorff_kernel<<<grid, NT>>>(pred, targ, out, n);
}